// round 5
// baseline (speedup 1.0000x reference)
#include <cuda_runtime.h>
#include <cuda_bf16.h>

typedef unsigned int u32;

#define B_   8
#define N_   1024
#define C_   1024
#define H_   16
#define D_   64
#define M_   (B_ * N_)     // 8192
#define QKVC 3072
#define BH_  (B_ * H_)     // 128

// ---------------- allocation-free scratch (device globals) ----------------
__device__ __align__(256) __nv_bfloat16 g_xh[(size_t)M_ * C_],  g_xl[(size_t)M_ * C_];
__device__ __align__(256) __nv_bfloat16 g_wqh[(size_t)QKVC * C_], g_wql[(size_t)QKVC * C_];
__device__ __align__(256) __nv_bfloat16 g_wph[(size_t)C_ * C_],  g_wpl[(size_t)C_ * C_];
__device__ __align__(256) __nv_bfloat16 g_qh[(size_t)BH_ * N_ * D_], g_ql[(size_t)BH_ * N_ * D_];
__device__ __align__(256) __nv_bfloat16 g_kh[(size_t)BH_ * N_ * D_], g_kl[(size_t)BH_ * N_ * D_];
__device__ __align__(256) __nv_bfloat16 g_vTh[(size_t)BH_ * D_ * N_], g_vTl[(size_t)BH_ * D_ * N_];
__device__ __align__(256) __nv_bfloat16 g_ah[(size_t)BH_ * N_ * N_], g_al[(size_t)BH_ * N_ * N_];
__device__ __align__(256) __nv_bfloat16 g_ch[(size_t)M_ * C_],  g_cl[(size_t)M_ * C_];

// ---------------- helpers ----------------
__device__ __forceinline__ u32 smem_u32(const void* p) {
    u32 a;
    asm("{ .reg .u64 t; cvta.to.shared.u64 t, %1; cvt.u32.u64 %0, t; }" : "=r"(a) : "l"(p));
    return a;
}
#define CP16(dst, src) \
    asm volatile("cp.async.cg.shared.global [%0], [%1], 16;" :: "r"(dst), "l"(src) : "memory")
#define CP_COMMIT() asm volatile("cp.async.commit_group;" ::: "memory")
#define CP_WAIT(n)  asm volatile("cp.async.wait_group %0;" :: "n"(n) : "memory")

__device__ __forceinline__ void ldm4(u32& r0, u32& r1, u32& r2, u32& r3, u32 a) {
    asm volatile("ldmatrix.sync.aligned.m8n8.x4.shared.b16 {%0,%1,%2,%3}, [%4];"
        : "=r"(r0), "=r"(r1), "=r"(r2), "=r"(r3) : "r"(a));
}
__device__ __forceinline__ void mma16816(float* c, const u32* a, const u32* b) {
    asm volatile(
        "mma.sync.aligned.m16n8k16.row.col.f32.bf16.bf16.f32 "
        "{%0,%1,%2,%3}, {%4,%5,%6,%7}, {%8,%9}, {%0,%1,%2,%3};"
        : "+f"(c[0]), "+f"(c[1]), "+f"(c[2]), "+f"(c[3])
        : "r"(a[0]), "r"(a[1]), "r"(a[2]), "r"(a[3]), "r"(b[0]), "r"(b[1]));
}
__device__ __forceinline__ void splitf(float v, __nv_bfloat16& h, __nv_bfloat16& l) {
    h = __float2bfloat16(v);
    l = __float2bfloat16(v - __bfloat162float(h));
}

// ---------------------------------------------------------------------------
// Split-bf16 HMMA GEMM, 512 threads / 16 warps (4 warps per SMSP).
// MODE 0: tile 128x128, QKV (x * wqkvT)    -> scatter q(scaled)/k/vT hi+lo
// MODE 2: tile 256x64,  AV (attn * vT, bh) -> ctx hi+lo
// MODE 3: tile 128x128, OUT (ctx * wprojT) -> fp32 out + bias
// Warp = 32x32 sub-tile (MA=2, NA=4). 3-stage cp.async ring, 80B smem pitch.
// ---------------------------------------------------------------------------
template <int MODE>
__global__ void __launch_bounds__(512, 1) mma_gemm(float* __restrict__ out_f32,
                                                   const float* __restrict__ bias)
{
    constexpr int MTILE = (MODE == 2) ? 256 : 128;
    constexpr int NTILE = (MODE == 2) ? 64 : 128;
    constexpr int NC    = 32;                    // K = 1024, chunk 32
    constexpr int MA    = 2;
    constexpr int NA    = 4;
    constexpr int APART = MTILE * 80;
    constexpr int BPART = NTILE * 80;
    constexpr int STAGE = 2 * APART + 2 * BPART;

    extern __shared__ char smem[];
    const u32 sb   = smem_u32(smem);
    const int tid  = threadIdx.x;
    const int wid  = tid >> 5, lane = tid & 31;
    const int g    = lane >> 2, t = lane & 3;
    const int bn   = blockIdx.x * NTILE;
    const int bm   = blockIdx.y * MTILE;
    const int z    = blockIdx.z;
    const int wm   = (MODE == 2) ? (wid & 7) * 32 : (wid & 3) * 32;
    const int wn   = (MODE == 2) ? (wid >> 3) * 32 : (wid >> 2) * 32;

    const __nv_bfloat16 *Ah, *Al, *Bh, *Bl;
    int lda, ldb;
    if (MODE == 0) {
        Ah = g_xh + (size_t)bm * C_;  Al = g_xl + (size_t)bm * C_;  lda = C_;
        Bh = g_wqh + (size_t)bn * C_; Bl = g_wql + (size_t)bn * C_; ldb = C_;
    } else if (MODE == 2) {
        size_t ao = (size_t)z * N_ * N_ + (size_t)bm * N_;
        size_t bo = (size_t)z * D_ * N_;
        Ah = g_ah + ao;  Al = g_al + ao;  lda = N_;
        Bh = g_vTh + bo; Bl = g_vTl + bo; ldb = N_;
    } else {
        Ah = g_ch + (size_t)bm * C_;  Al = g_cl + (size_t)bm * C_;  lda = C_;
        Bh = g_wph + (size_t)bn * C_; Bl = g_wpl + (size_t)bn * C_; ldb = C_;
    }

    float acc[MA][NA][4];
    #pragma unroll
    for (int i = 0; i < MA; i++)
        #pragma unroll
        for (int j = 0; j < NA; j++)
            #pragma unroll
            for (int r = 0; r < 4; r++) acc[i][j][r] = 0.0f;

    auto issue_loads = [&](int ck, int s) {
        const int kofs = ck * 32;
        const u32 base = sb + s * STAGE;
        #pragma unroll
        for (int i = tid; i < MTILE * 4; i += 512) {
            int r = i >> 2, sgm = i & 3;
            u32 off = (u32)(r * 80 + sgm * 16);
            CP16(base + off,         Ah + (size_t)r * lda + kofs + sgm * 8);
            CP16(base + APART + off, Al + (size_t)r * lda + kofs + sgm * 8);
        }
        #pragma unroll
        for (int i = tid; i < NTILE * 4; i += 512) {
            int r = i >> 2, sgm = i & 3;
            u32 off = (u32)(r * 80 + sgm * 16);
            CP16(base + 2 * APART + off,         Bh + (size_t)r * ldb + kofs + sgm * 8);
            CP16(base + 2 * APART + BPART + off, Bl + (size_t)r * ldb + kofs + sgm * 8);
        }
        CP_COMMIT();
    };

    const u32 arow = (u32)((wm + (lane & 15)) * 80 + ((lane >> 4) << 4));
    const u32 brow = (u32)((wn + (lane & 7) + ((lane >> 4) << 3)) * 80 + (((lane >> 3) & 1) << 4));

    auto do_compute = [&](int s) {
        const u32 abase = sb + s * STAGE;
        const u32 bbase = abase + 2 * APART;
        #pragma unroll
        for (int ks = 0; ks < 2; ks++) {
            const u32 kb = ks * 32;
            u32 a_hi[MA][4], a_lo[MA][4], b_hi[NA][2], b_lo[NA][2];
            #pragma unroll
            for (int ma = 0; ma < MA; ma++) {
                u32 ad = abase + arow + ma * 16 * 80 + kb;
                ldm4(a_hi[ma][0], a_hi[ma][1], a_hi[ma][2], a_hi[ma][3], ad);
                ldm4(a_lo[ma][0], a_lo[ma][1], a_lo[ma][2], a_lo[ma][3], ad + APART);
            }
            #pragma unroll
            for (int p = 0; p < NA / 2; p++) {
                u32 bd = bbase + brow + p * 16 * 80 + kb;
                ldm4(b_hi[2*p][0], b_hi[2*p][1], b_hi[2*p+1][0], b_hi[2*p+1][1], bd);
                ldm4(b_lo[2*p][0], b_lo[2*p][1], b_lo[2*p+1][0], b_lo[2*p+1][1], bd + BPART);
            }
            #pragma unroll
            for (int ma = 0; ma < MA; ma++)
                #pragma unroll
                for (int na = 0; na < NA; na++) {
                    mma16816(acc[ma][na], a_hi[ma], b_hi[na]);
                    mma16816(acc[ma][na], a_hi[ma], b_lo[na]);
                    mma16816(acc[ma][na], a_lo[ma], b_hi[na]);
                }
        }
    };

    issue_loads(0, 0);
    issue_loads(1, 1);
    for (int ck = 0; ck < NC; ck++) {
        const int s = ck % 3;
        if (ck + 2 < NC) { issue_loads(ck + 2, (ck + 2) % 3); CP_WAIT(2); }
        else if (ck + 1 < NC) { CP_WAIT(1); }
        else { CP_WAIT(0); }
        __syncthreads();
        do_compute(s);
        __syncthreads();
    }

    // ---- epilogue ----
    #pragma unroll
    for (int ma = 0; ma < MA; ma++)
        #pragma unroll
        for (int na = 0; na < NA; na++)
            #pragma unroll
            for (int half = 0; half < 2; half++) {
                const int row = bm + wm + ma * 16 + g + half * 8;
                const int col = bn + wn + na * 8 + t * 2;
                float v0 = acc[ma][na][half * 2 + 0];
                float v1 = acc[ma][na][half * 2 + 1];

                if (MODE == 3) {
                    float* dst = out_f32 + (size_t)row * C_ + col;
                    *(float2*)dst = make_float2(v0 + bias[col], v1 + bias[col + 1]);
                } else if (MODE == 2) {
                    const int b8 = z >> 4, h = z & 15;
                    const size_t base = ((size_t)(b8 * N_ + row)) * C_ + h * 64 + col;
                    __nv_bfloat16 h0, l0, h1, l1;
                    splitf(v0, h0, l0); splitf(v1, h1, l1);
                    *(__nv_bfloat162*)(g_ch + base) = __nv_bfloat162(h0, h1);
                    *(__nv_bfloat162*)(g_cl + base) = __nv_bfloat162(l0, l1);
                } else {  // MODE 0
                    const int which = col >> 10;
                    const int c     = col & 1023;
                    const int h     = c >> 6;
                    const int d0    = c & 63;
                    const int b8    = row >> 10;
                    const int n     = row & 1023;
                    const int bh    = b8 * H_ + h;
                    if (which == 0) {
                        __nv_bfloat16 h0, l0, h1, l1;
                        splitf(v0 * 0.125f, h0, l0); splitf(v1 * 0.125f, h1, l1);
                        const size_t base = ((size_t)bh * N_ + n) * D_ + d0;
                        *(__nv_bfloat162*)(g_qh + base) = __nv_bfloat162(h0, h1);
                        *(__nv_bfloat162*)(g_ql + base) = __nv_bfloat162(l0, l1);
                    } else if (which == 1) {
                        __nv_bfloat16 h0, l0, h1, l1;
                        splitf(v0, h0, l0); splitf(v1, h1, l1);
                        const size_t base = ((size_t)bh * N_ + n) * D_ + d0;
                        *(__nv_bfloat162*)(g_kh + base) = __nv_bfloat162(h0, h1);
                        *(__nv_bfloat162*)(g_kl + base) = __nv_bfloat162(l0, l1);
                    } else {
                        __nv_bfloat16 h0, l0, h1, l1;
                        splitf(v0, h0, l0); splitf(v1, h1, l1);
                        const size_t vb = (size_t)bh * D_ * N_ + n;
                        g_vTh[vb + (size_t)d0 * N_]       = h0;
                        g_vTh[vb + (size_t)(d0 + 1) * N_] = h1;
                        g_vTl[vb + (size_t)d0 * N_]       = l0;
                        g_vTl[vb + (size_t)(d0 + 1) * N_] = l1;
                    }
                }
            }
}

// ---------------------------------------------------------------------------
// Fused S = qk^T -> softmax -> attn fp32 out + bf16 split (32-row slab).
// 512 threads / 16 warps: warp = 16x16 sub-tile of the 32x128 chunk.
// ---------------------------------------------------------------------------
#define Q_OFF  0
#define QL_OFF 4608
#define K_OFF  9216
#define KSTG   36864
#define KL_OFF 18432
#define S_OFF  82944
#define S_PIT  4144
#define SS_SMEM (S_OFF + 32 * S_PIT)   // 215552

__global__ void __launch_bounds__(512, 1) sscore_kernel(float* __restrict__ attn)
{
    extern __shared__ char smem[];
    const u32 sb   = smem_u32(smem);
    const int tid  = threadIdx.x;
    const int wid  = tid >> 5, lane = tid & 31;
    const int g    = lane >> 2, t = lane & 3;

    const int bh   = blockIdx.x >> 5;
    const int row0 = (blockIdx.x & 31) * 32;
    const int wm   = (wid & 1) * 16;
    const int wn   = (wid >> 1) * 16;

    const __nv_bfloat16* Qh = g_qh + ((size_t)bh * N_ + row0) * D_;
    const __nv_bfloat16* Ql = g_ql + ((size_t)bh * N_ + row0) * D_;
    const __nv_bfloat16* Kh = g_kh + (size_t)bh * N_ * D_;
    const __nv_bfloat16* Kl = g_kl + (size_t)bh * N_ * D_;

    // Q slab: 32 rows x 128B, pitch 144 (512 threads: one 16B seg each for hi+lo)
    if (tid < 256) {
        int r = tid >> 3, sgm = tid & 7;
        u32 off = (u32)(r * 144 + sgm * 16);
        *(float4*)(smem + Q_OFF + off)  = *(const float4*)(Qh + r * D_ + sgm * 8);
        *(float4*)(smem + QL_OFF + off) = *(const float4*)(Ql + r * D_ + sgm * 8);
    }

    auto issueK = [&](int c, int s) {
        const u32 base = sb + K_OFF + s * KSTG;
        const size_t ko = (size_t)c * 128 * D_;
        #pragma unroll
        for (int i = tid; i < 128 * 8; i += 512) {
            int r = i >> 3, sgm = i & 7;
            u32 off = (u32)(r * 144 + sgm * 16);
            CP16(base + off,          Kh + ko + r * D_ + sgm * 8);
            CP16(base + KL_OFF + off, Kl + ko + r * D_ + sgm * 8);
        }
        CP_COMMIT();
    };

    const u32 arow = (u32)((wm + (lane & 15)) * 144 + ((lane >> 4) << 4));
    const u32 brow = (u32)((wn + (lane & 7) + ((lane >> 4) << 3)) * 144 + (((lane >> 3) & 1) << 4));

    issueK(0, 0);
    issueK(1, 1);
    for (int c = 0; c < 8; c++) {
        if (c < 7) CP_WAIT(1); else CP_WAIT(0);
        __syncthreads();

        const u32 kb0 = sb + K_OFF + (c & 1) * KSTG;
        float acc[2][4];
        #pragma unroll
        for (int j = 0; j < 2; j++)
            #pragma unroll
            for (int r = 0; r < 4; r++) acc[j][r] = 0.0f;

        #pragma unroll
        for (int ks = 0; ks < 4; ks++) {
            const u32 kb = ks * 32;
            u32 a_hi[4], a_lo[4], b_hi[2][2], b_lo[2][2];
            u32 ad = sb + Q_OFF + arow + kb;
            ldm4(a_hi[0], a_hi[1], a_hi[2], a_hi[3], ad);
            ldm4(a_lo[0], a_lo[1], a_lo[2], a_lo[3], ad + QL_OFF);
            u32 bd = kb0 + brow + kb;
            ldm4(b_hi[0][0], b_hi[0][1], b_hi[1][0], b_hi[1][1], bd);
            ldm4(b_lo[0][0], b_lo[0][1], b_lo[1][0], b_lo[1][1], bd + KL_OFF);
            #pragma unroll
            for (int na = 0; na < 2; na++) {
                mma16816(acc[na], a_hi, b_hi[na]);
                mma16816(acc[na], a_hi, b_lo[na]);
                mma16816(acc[na], a_lo, b_hi[na]);
            }
        }

        #pragma unroll
        for (int na = 0; na < 2; na++)
            #pragma unroll
            for (int half = 0; half < 2; half++) {
                int row = wm + g + half * 8;
                int col = c * 128 + wn + na * 8 + t * 2;
                *(float2*)(smem + S_OFF + row * S_PIT + col * 4) =
                    make_float2(acc[na][half * 2], acc[na][half * 2 + 1]);
            }

        __syncthreads();
        if (c + 2 < 8) issueK(c + 2, c & 1);
    }

    // ---- softmax over rows (2 rows per warp) + outputs ----
    #pragma unroll
    for (int rr = 0; rr < 2; rr++) {
        const int r = wid * 2 + rr;
        const float* Srow = (const float*)(smem + S_OFF + r * S_PIT);
        float4 f[8];
        float m = -1e30f;
        #pragma unroll
        for (int i = 0; i < 8; i++) {
            f[i] = *(const float4*)(Srow + (lane + i * 32) * 4);
            m = fmaxf(m, fmaxf(fmaxf(f[i].x, f[i].y), fmaxf(f[i].z, f[i].w)));
        }
        #pragma unroll
        for (int o = 16; o > 0; o >>= 1) m = fmaxf(m, __shfl_xor_sync(0xffffffffu, m, o));
        float s = 0.0f;
        #pragma unroll
        for (int i = 0; i < 8; i++) {
            f[i].x = __expf(f[i].x - m); f[i].y = __expf(f[i].y - m);
            f[i].z = __expf(f[i].z - m); f[i].w = __expf(f[i].w - m);
            s += f[i].x + f[i].y + f[i].z + f[i].w;
        }
        #pragma unroll
        for (int o = 16; o > 0; o >>= 1) s += __shfl_xor_sync(0xffffffffu, s, o);
        const float inv = 1.0f / s;

        const size_t gr = (size_t)bh * N_ + row0 + r;
        float* ap = attn + gr * N_;
        __nv_bfloat162* ahp = ((__nv_bfloat162*)g_ah) + gr * (N_ / 2);
        __nv_bfloat162* alp = ((__nv_bfloat162*)g_al) + gr * (N_ / 2);
        #pragma unroll
        for (int i = 0; i < 8; i++) {
            float4 p = make_float4(f[i].x * inv, f[i].y * inv, f[i].z * inv, f[i].w * inv);
            *(float4*)(ap + (lane + i * 32) * 4) = p;
            __nv_bfloat16 h0, l0, h1, l1, h2, l2, h3, l3;
            splitf(p.x, h0, l0); splitf(p.y, h1, l1);
            splitf(p.z, h2, l2); splitf(p.w, h3, l3);
            const int c2 = (lane + i * 32) * 2;
            ahp[c2]     = __nv_bfloat162(h0, h1);
            ahp[c2 + 1] = __nv_bfloat162(h2, h3);
            alp[c2]     = __nv_bfloat162(l0, l1);
            alp[c2 + 1] = __nv_bfloat162(l2, l3);
        }
    }
}

// ---------------- conversion kernels ----------------
__global__ void __launch_bounds__(256) conv_x(const float* __restrict__ s)
{
    int i = blockIdx.x * 256 + threadIdx.x;
    float4 v = ((const float4*)s)[i];
    __nv_bfloat16 h0, l0, h1, l1, h2, l2, h3, l3;
    splitf(v.x, h0, l0); splitf(v.y, h1, l1);
    splitf(v.z, h2, l2); splitf(v.w, h3, l3);
    __nv_bfloat162* hp = (__nv_bfloat162*)g_xh;
    __nv_bfloat162* lp = (__nv_bfloat162*)g_xl;
    hp[i * 2]     = __nv_bfloat162(h0, h1);
    hp[i * 2 + 1] = __nv_bfloat162(h2, h3);
    lp[i * 2]     = __nv_bfloat162(l0, l1);
    lp[i * 2 + 1] = __nv_bfloat162(l2, l3);
}

template <int W>
__global__ void __launch_bounds__(256) conv_wT(const float* __restrict__ s)
{
    constexpr int R  = C_;
    constexpr int Cc = (W == 0) ? QKVC : C_;
    __nv_bfloat16* dh = (W == 0) ? g_wqh : g_wph;
    __nv_bfloat16* dl = (W == 0) ? g_wql : g_wpl;

    __shared__ float tbuf[32][33];
    const int tx = threadIdx.x & 31, ty = threadIdx.x >> 5;
    const int c0 = blockIdx.x * 32, r0 = blockIdx.y * 32;
    #pragma unroll
    for (int j = 0; j < 4; j++)
        tbuf[ty + j * 8][tx] = s[(size_t)(r0 + ty + j * 8) * Cc + c0 + tx];
    __syncthreads();
    #pragma unroll
    for (int j = 0; j < 4; j++) {
        int i = ty + j * 8;
        float v = tbuf[tx][i];
        __nv_bfloat16 hh, ll;
        splitf(v, hh, ll);
        size_t idx = (size_t)(c0 + i) * R + r0 + tx;
        dh[idx] = hh;
        dl[idx] = ll;
    }
}

// ---------------------------------------------------------------------------
extern "C" void kernel_launch(void* const* d_in, const int* in_sizes, int n_in,
                              void* d_out, int out_size)
{
    const float* x      = (const float*)d_in[0];
    const float* w_qkv  = (const float*)d_in[1];
    const float* w_proj = (const float*)d_in[2];
    const float* b_proj = (const float*)d_in[3];
    float* out  = (float*)d_out;
    float* attn = out + (size_t)M_ * C_;

    const int S128 = 3 * (2 * 128 * 80 + 2 * 128 * 80);   // 122880
    const int S256 = 3 * (2 * 256 * 80 + 2 * 64 * 80);    // 153600

    cudaFuncSetAttribute(mma_gemm<0>, cudaFuncAttributeMaxDynamicSharedMemorySize, S128);
    cudaFuncSetAttribute(mma_gemm<2>, cudaFuncAttributeMaxDynamicSharedMemorySize, S256);
    cudaFuncSetAttribute(mma_gemm<3>, cudaFuncAttributeMaxDynamicSharedMemorySize, S128);
    cudaFuncSetAttribute(sscore_kernel, cudaFuncAttributeMaxDynamicSharedMemorySize, SS_SMEM);

    // 1) input conversions
    conv_x<<<M_ * C_ / 1024, 256>>>(x);
    conv_wT<0><<<dim3(QKVC / 32, C_ / 32), 256>>>(w_qkv);
    conv_wT<1><<<dim3(C_ / 32, C_ / 32), 256>>>(w_proj);

    // 2) QKV GEMM -> q(scaled)/k/vT splits
    mma_gemm<0><<<dim3(QKVC / 128, M_ / 128), 512, S128>>>(nullptr, nullptr);

    // 3) fused S + softmax + attn write + bf16 split
    sscore_kernel<<<BH_ * 32, 512, SS_SMEM>>>(attn);

    // 4) ctx = attn @ V (tile 256x64)
    mma_gemm<2><<<dim3(1, N_ / 256, BH_), 512, S256>>>(nullptr, nullptr);

    // 5) out = ctx @ w_proj + bias
    mma_gemm<3><<<dim3(C_ / 128, M_ / 128), 512, S128>>>(out, b_proj);
}

// round 6
// speedup vs baseline: 1.0158x; 1.0158x over previous
#include <cuda_runtime.h>
#include <cuda_bf16.h>

typedef unsigned int u32;

#define B_   8
#define N_   1024
#define C_   1024
#define H_   16
#define D_   64
#define M_   (B_ * N_)     // 8192
#define QKVC 3072
#define BH_  (B_ * H_)     // 128

// ---------------- allocation-free scratch (device globals) ----------------
__device__ __align__(256) __nv_bfloat16 g_xh[(size_t)M_ * C_],  g_xl[(size_t)M_ * C_];
__device__ __align__(256) __nv_bfloat16 g_wqh[(size_t)QKVC * C_], g_wql[(size_t)QKVC * C_];
__device__ __align__(256) __nv_bfloat16 g_wph[(size_t)C_ * C_],  g_wpl[(size_t)C_ * C_];
__device__ __align__(256) __nv_bfloat16 g_qh[(size_t)BH_ * N_ * D_], g_ql[(size_t)BH_ * N_ * D_];
__device__ __align__(256) __nv_bfloat16 g_kh[(size_t)BH_ * N_ * D_], g_kl[(size_t)BH_ * N_ * D_];
__device__ __align__(256) __nv_bfloat16 g_vTh[(size_t)BH_ * D_ * N_], g_vTl[(size_t)BH_ * D_ * N_];
__device__ __align__(256) __nv_bfloat16 g_ch[(size_t)M_ * C_],  g_cl[(size_t)M_ * C_];

// ---------------- helpers ----------------
__device__ __forceinline__ u32 smem_u32(const void* p) {
    u32 a;
    asm("{ .reg .u64 t; cvta.to.shared.u64 t, %1; cvt.u32.u64 %0, t; }" : "=r"(a) : "l"(p));
    return a;
}
#define CP16(dst, src) \
    asm volatile("cp.async.cg.shared.global [%0], [%1], 16;" :: "r"(dst), "l"(src) : "memory")
#define CP_COMMIT() asm volatile("cp.async.commit_group;" ::: "memory")
#define CP_WAIT(n)  asm volatile("cp.async.wait_group %0;" :: "n"(n) : "memory")

__device__ __forceinline__ void ldm4(u32& r0, u32& r1, u32& r2, u32& r3, u32 a) {
    asm volatile("ldmatrix.sync.aligned.m8n8.x4.shared.b16 {%0,%1,%2,%3}, [%4];"
        : "=r"(r0), "=r"(r1), "=r"(r2), "=r"(r3) : "r"(a));
}
__device__ __forceinline__ void mma16816(float* c, const u32* a, const u32* b) {
    asm volatile(
        "mma.sync.aligned.m16n8k16.row.col.f32.bf16.bf16.f32 "
        "{%0,%1,%2,%3}, {%4,%5,%6,%7}, {%8,%9}, {%0,%1,%2,%3};"
        : "+f"(c[0]), "+f"(c[1]), "+f"(c[2]), "+f"(c[3])
        : "r"(a[0]), "r"(a[1]), "r"(a[2]), "r"(a[3]), "r"(b[0]), "r"(b[1]));
}
__device__ __forceinline__ void splitf(float v, __nv_bfloat16& h, __nv_bfloat16& l) {
    h = __float2bfloat16(v);
    l = __float2bfloat16(v - __bfloat162float(h));
}

// ---------------------------------------------------------------------------
// Split-bf16 HMMA GEMM (r4 config: 256 threads, 8 warps, MA4 NA4, 3-stage ring)
// MODE 0: QKV (x * wqkvT)    -> scatter q(scaled)/k/vT hi+lo
// MODE 3: OUT (ctx * wprojT) -> fp32 out + bias
// ---------------------------------------------------------------------------
template <int MODE>
__global__ void __launch_bounds__(256, 1) mma_gemm(float* __restrict__ out_f32,
                                                   const float* __restrict__ bias)
{
    constexpr int NTILE = 128;
    constexpr int NC    = 32;
    constexpr int MA    = 4;
    constexpr int NA    = 4;
    constexpr int APART = 128 * 80;
    constexpr int BPART = 128 * 80;
    constexpr int STAGE = 2 * APART + 2 * BPART;

    extern __shared__ char smem[];
    const u32 sb   = smem_u32(smem);
    const int tid  = threadIdx.x;
    const int wid  = tid >> 5, lane = tid & 31;
    const int g    = lane >> 2, t = lane & 3;
    const int bn   = blockIdx.x * NTILE;
    const int bm   = blockIdx.y * 128;
    const int wm   = (wid & 1) * 64;
    const int wn   = (wid >> 1) * 32;

    const __nv_bfloat16 *Ah, *Al, *Bh, *Bl;
    if (MODE == 0) {
        Ah = g_xh + (size_t)bm * C_;  Al = g_xl + (size_t)bm * C_;
        Bh = g_wqh + (size_t)bn * C_; Bl = g_wql + (size_t)bn * C_;
    } else {
        Ah = g_ch + (size_t)bm * C_;  Al = g_cl + (size_t)bm * C_;
        Bh = g_wph + (size_t)bn * C_; Bl = g_wpl + (size_t)bn * C_;
    }

    float acc[MA][NA][4];
    #pragma unroll
    for (int i = 0; i < MA; i++)
        #pragma unroll
        for (int j = 0; j < NA; j++)
            #pragma unroll
            for (int r = 0; r < 4; r++) acc[i][j][r] = 0.0f;

    auto issue_loads = [&](int ck, int s) {
        const int kofs = ck * 32;
        const u32 base = sb + s * STAGE;
        #pragma unroll
        for (int i = tid; i < 128 * 4; i += 256) {
            int r = i >> 2, sgm = i & 3;
            u32 off = (u32)(r * 80 + sgm * 16);
            CP16(base + off,         Ah + (size_t)r * C_ + kofs + sgm * 8);
            CP16(base + APART + off, Al + (size_t)r * C_ + kofs + sgm * 8);
        }
        #pragma unroll
        for (int i = tid; i < 128 * 4; i += 256) {
            int r = i >> 2, sgm = i & 3;
            u32 off = (u32)(r * 80 + sgm * 16);
            CP16(base + 2 * APART + off,         Bh + (size_t)r * C_ + kofs + sgm * 8);
            CP16(base + 2 * APART + BPART + off, Bl + (size_t)r * C_ + kofs + sgm * 8);
        }
        CP_COMMIT();
    };

    const u32 arow = (u32)((wm + (lane & 15)) * 80 + ((lane >> 4) << 4));
    const u32 brow = (u32)((wn + (lane & 7) + ((lane >> 4) << 3)) * 80 + (((lane >> 3) & 1) << 4));

    auto do_compute = [&](int s) {
        const u32 abase = sb + s * STAGE;
        const u32 bbase = abase + 2 * APART;
        #pragma unroll
        for (int ks = 0; ks < 2; ks++) {
            const u32 kb = ks * 32;
            u32 a_hi[MA][4], a_lo[MA][4], b_hi[NA][2], b_lo[NA][2];
            #pragma unroll
            for (int ma = 0; ma < MA; ma++) {
                u32 ad = abase + arow + ma * 16 * 80 + kb;
                ldm4(a_hi[ma][0], a_hi[ma][1], a_hi[ma][2], a_hi[ma][3], ad);
                ldm4(a_lo[ma][0], a_lo[ma][1], a_lo[ma][2], a_lo[ma][3], ad + APART);
            }
            #pragma unroll
            for (int p = 0; p < NA / 2; p++) {
                u32 bd = bbase + brow + p * 16 * 80 + kb;
                ldm4(b_hi[2*p][0], b_hi[2*p][1], b_hi[2*p+1][0], b_hi[2*p+1][1], bd);
                ldm4(b_lo[2*p][0], b_lo[2*p][1], b_lo[2*p+1][0], b_lo[2*p+1][1], bd + BPART);
            }
            #pragma unroll
            for (int ma = 0; ma < MA; ma++)
                #pragma unroll
                for (int na = 0; na < NA; na++) {
                    mma16816(acc[ma][na], a_hi[ma], b_hi[na]);
                    mma16816(acc[ma][na], a_hi[ma], b_lo[na]);
                    mma16816(acc[ma][na], a_lo[ma], b_hi[na]);
                }
        }
    };

    issue_loads(0, 0);
    issue_loads(1, 1);
    for (int ck = 0; ck < NC; ck++) {
        const int s = ck % 3;
        if (ck + 2 < NC) { issue_loads(ck + 2, (ck + 2) % 3); CP_WAIT(2); }
        else if (ck + 1 < NC) { CP_WAIT(1); }
        else { CP_WAIT(0); }
        __syncthreads();
        do_compute(s);
        __syncthreads();
    }

    // ---- epilogue ----
    #pragma unroll
    for (int ma = 0; ma < MA; ma++)
        #pragma unroll
        for (int na = 0; na < NA; na++)
            #pragma unroll
            for (int half = 0; half < 2; half++) {
                const int row = bm + wm + ma * 16 + g + half * 8;
                const int col = bn + wn + na * 8 + t * 2;
                float v0 = acc[ma][na][half * 2 + 0];
                float v1 = acc[ma][na][half * 2 + 1];

                if (MODE == 3) {
                    float* dst = out_f32 + (size_t)row * C_ + col;
                    *(float2*)dst = make_float2(v0 + bias[col], v1 + bias[col + 1]);
                } else {  // MODE 0
                    const int which = col >> 10;
                    const int c     = col & 1023;
                    const int h     = c >> 6;
                    const int d0    = c & 63;
                    const int b8    = row >> 10;
                    const int n     = row & 1023;
                    const int bh    = b8 * H_ + h;
                    if (which == 0) {
                        __nv_bfloat16 h0, l0, h1, l1;
                        splitf(v0 * 0.125f, h0, l0); splitf(v1 * 0.125f, h1, l1);
                        const size_t base = ((size_t)bh * N_ + n) * D_ + d0;
                        *(__nv_bfloat162*)(g_qh + base) = __nv_bfloat162(h0, h1);
                        *(__nv_bfloat162*)(g_ql + base) = __nv_bfloat162(l0, l1);
                    } else if (which == 1) {
                        __nv_bfloat16 h0, l0, h1, l1;
                        splitf(v0, h0, l0); splitf(v1, h1, l1);
                        const size_t base = ((size_t)bh * N_ + n) * D_ + d0;
                        *(__nv_bfloat162*)(g_kh + base) = __nv_bfloat162(h0, h1);
                        *(__nv_bfloat162*)(g_kl + base) = __nv_bfloat162(l0, l1);
                    } else {
                        __nv_bfloat16 h0, l0, h1, l1;
                        splitf(v0, h0, l0); splitf(v1, h1, l1);
                        const size_t vb = (size_t)bh * D_ * N_ + n;
                        g_vTh[vb + (size_t)d0 * N_]       = h0;
                        g_vTh[vb + (size_t)(d0 + 1) * N_] = h1;
                        g_vTl[vb + (size_t)d0 * N_]       = l0;
                        g_vTl[vb + (size_t)(d0 + 1) * N_] = l1;
                    }
                }
            }
}

// ---------------------------------------------------------------------------
// Fused attention: S = qk^T -> softmax -> attn fp32 write -> P@V -> ctx split.
// Per block: one (bh, 32-row q slab). 512 threads / 16 warps.
// Smem: Q hi/lo (9216) | K 2-stage ring (73728; reused for V ring in phase C)
//       | S region 32 x 4144 (fp32 scores, then P hi/lo bf16 in place).
// ---------------------------------------------------------------------------
#define Q_OFF  0
#define QL_OFF 4608
#define K_OFF  9216
#define KSTG   36864
#define KL_OFF 18432
#define VSTG   34816
#define VL_OFF 17408
#define S_OFF  82944
#define S_PIT  4144
#define FA_SMEM (S_OFF + 32 * S_PIT)   // 215552

__global__ void __launch_bounds__(512, 1) fused_attn(float* __restrict__ attn)
{
    extern __shared__ char smem[];
    const u32 sb   = smem_u32(smem);
    const int tid  = threadIdx.x;
    const int wid  = tid >> 5, lane = tid & 31;
    const int g    = lane >> 2, t = lane & 3;

    const int bh   = blockIdx.x >> 5;
    const int row0 = (blockIdx.x & 31) * 32;
    const int b8   = bh >> 4, h = bh & 15;

    const __nv_bfloat16* Qh = g_qh + ((size_t)bh * N_ + row0) * D_;
    const __nv_bfloat16* Ql = g_ql + ((size_t)bh * N_ + row0) * D_;
    const __nv_bfloat16* Kh = g_kh + (size_t)bh * N_ * D_;
    const __nv_bfloat16* Kl = g_kl + (size_t)bh * N_ * D_;
    const __nv_bfloat16* Vh = g_vTh + (size_t)bh * D_ * N_;
    const __nv_bfloat16* Vl = g_vTl + (size_t)bh * D_ * N_;

    // Q slab: 32 rows x 128B, pitch 144
    if (tid < 256) {
        int r = tid >> 3, sgm = tid & 7;
        u32 off = (u32)(r * 144 + sgm * 16);
        *(float4*)(smem + Q_OFF + off)  = *(const float4*)(Qh + r * D_ + sgm * 8);
        *(float4*)(smem + QL_OFF + off) = *(const float4*)(Ql + r * D_ + sgm * 8);
    }

    auto issueK = [&](int c, int s) {
        const u32 base = sb + K_OFF + s * KSTG;
        const size_t ko = (size_t)c * 128 * D_;
        #pragma unroll
        for (int i = tid; i < 128 * 8; i += 512) {
            int r = i >> 3, sgm = i & 7;
            u32 off = (u32)(r * 144 + sgm * 16);
            CP16(base + off,          Kh + ko + r * D_ + sgm * 8);
            CP16(base + KL_OFF + off, Kl + ko + r * D_ + sgm * 8);
        }
        CP_COMMIT();
    };

    // ================= Phase A: scores (warp = 16x16 of 32x128 chunk) =======
    {
        const int wm = (wid & 1) * 16;
        const int wn = (wid >> 1) * 16;
        const u32 arow = (u32)((wm + (lane & 15)) * 144 + ((lane >> 4) << 4));
        const u32 brow = (u32)((wn + (lane & 7) + ((lane >> 4) << 3)) * 144 + (((lane >> 3) & 1) << 4));

        issueK(0, 0);
        issueK(1, 1);
        for (int c = 0; c < 8; c++) {
            if (c < 7) CP_WAIT(1); else CP_WAIT(0);
            __syncthreads();

            const u32 kb0 = sb + K_OFF + (c & 1) * KSTG;
            float acc[2][4];
            #pragma unroll
            for (int j = 0; j < 2; j++)
                #pragma unroll
                for (int r = 0; r < 4; r++) acc[j][r] = 0.0f;

            #pragma unroll
            for (int ks = 0; ks < 4; ks++) {
                const u32 kb = ks * 32;
                u32 a_hi[4], a_lo[4], b_hi[2][2], b_lo[2][2];
                u32 ad = sb + Q_OFF + arow + kb;
                ldm4(a_hi[0], a_hi[1], a_hi[2], a_hi[3], ad);
                ldm4(a_lo[0], a_lo[1], a_lo[2], a_lo[3], ad + QL_OFF);
                u32 bd = kb0 + brow + kb;
                ldm4(b_hi[0][0], b_hi[0][1], b_hi[1][0], b_hi[1][1], bd);
                ldm4(b_lo[0][0], b_lo[0][1], b_lo[1][0], b_lo[1][1], bd + KL_OFF);
                #pragma unroll
                for (int na = 0; na < 2; na++) {
                    mma16816(acc[na], a_hi, b_hi[na]);
                    mma16816(acc[na], a_hi, b_lo[na]);
                    mma16816(acc[na], a_lo, b_hi[na]);
                }
            }

            #pragma unroll
            for (int na = 0; na < 2; na++)
                #pragma unroll
                for (int half = 0; half < 2; half++) {
                    int row = wm + g + half * 8;
                    int col = c * 128 + wn + na * 8 + t * 2;
                    *(float2*)(smem + S_OFF + row * S_PIT + col * 4) =
                        make_float2(acc[na][half * 2], acc[na][half * 2 + 1]);
                }

            __syncthreads();
            if (c + 2 < 8) issueK(c + 2, c & 1);
        }
    }

    // ========== Phase B: softmax; write attn fp32; P hi/lo bf16 into smem ===
    #pragma unroll
    for (int rr = 0; rr < 2; rr++) {
        const int r = wid * 2 + rr;
        char* Srow = smem + S_OFF + r * S_PIT;
        float4 f[8];
        float m = -1e30f;
        #pragma unroll
        for (int i = 0; i < 8; i++) {
            f[i] = *(const float4*)(Srow + (lane + i * 32) * 16);
            m = fmaxf(m, fmaxf(fmaxf(f[i].x, f[i].y), fmaxf(f[i].z, f[i].w)));
        }
        #pragma unroll
        for (int o = 16; o > 0; o >>= 1) m = fmaxf(m, __shfl_xor_sync(0xffffffffu, m, o));
        float s = 0.0f;
        #pragma unroll
        for (int i = 0; i < 8; i++) {
            f[i].x = __expf(f[i].x - m); f[i].y = __expf(f[i].y - m);
            f[i].z = __expf(f[i].z - m); f[i].w = __expf(f[i].w - m);
            s += f[i].x + f[i].y + f[i].z + f[i].w;
        }
        #pragma unroll
        for (int o = 16; o > 0; o >>= 1) s += __shfl_xor_sync(0xffffffffu, s, o);
        const float inv = 1.0f / s;

        float* ap = attn + ((size_t)bh * N_ + row0 + r) * N_;
        #pragma unroll
        for (int i = 0; i < 8; i++) {
            float4 p = make_float4(f[i].x * inv, f[i].y * inv, f[i].z * inv, f[i].w * inv);
            *(float4*)(ap + (lane + i * 32) * 4) = p;     // posted store, overlaps phase C
            __nv_bfloat16 h0, l0, h1, l1, h2, l2, h3, l3;
            splitf(p.x, h0, l0); splitf(p.y, h1, l1);
            splitf(p.z, h2, l2); splitf(p.w, h3, l3);
            const int cb = (lane + i * 32) * 8;           // 4 bf16 = 8 bytes
            *(__nv_bfloat162*)(Srow + cb)          = __nv_bfloat162(h0, h1);
            *(__nv_bfloat162*)(Srow + cb + 4)      = __nv_bfloat162(h2, h3);
            *(__nv_bfloat162*)(Srow + 2048 + cb)     = __nv_bfloat162(l0, l1);
            *(__nv_bfloat162*)(Srow + 2048 + cb + 4) = __nv_bfloat162(l2, l3);
        }
    }
    __syncthreads();

    // ================= Phase C: ctx = P @ V (V ring reuses K ring smem) =====
    {
        auto issueV = [&](int c, int s) {
            const u32 base = sb + K_OFF + s * VSTG;
            const int ko = c * 128;
            #pragma unroll
            for (int i = tid; i < 64 * 16; i += 512) {
                int r = i >> 4, sgm = i & 15;
                u32 off = (u32)(r * 272 + sgm * 16);
                CP16(base + off,          Vh + (size_t)r * N_ + ko + sgm * 8);
                CP16(base + VL_OFF + off, Vl + (size_t)r * N_ + ko + sgm * 8);
            }
            CP_COMMIT();
        };

        const int wm  = (wid & 1) * 16;
        const int wn8 = (wid >> 1) * 8;
        const u32 arow = sb + S_OFF + (u32)((wm + (lane & 15)) * S_PIT + ((lane >> 4) << 4));
        const u32 brow = (u32)((wn8 + (lane & 7)) * 272 + ((lane >> 3) << 4));

        float acc_e[4] = {0, 0, 0, 0}, acc_o[4] = {0, 0, 0, 0};

        issueV(0, 0);
        issueV(1, 1);
        for (int c = 0; c < 8; c++) {
            if (c < 7) CP_WAIT(1); else CP_WAIT(0);
            __syncthreads();

            const u32 vb = sb + K_OFF + (c & 1) * VSTG;
            #pragma unroll
            for (int kp = 0; kp < 4; kp++) {          // ks pairs
                u32 bh4[4], bl4[4];
                u32 bd = vb + brow + kp * 64;
                ldm4(bh4[0], bh4[1], bh4[2], bh4[3], bd);
                ldm4(bl4[0], bl4[1], bl4[2], bl4[3], bd + VL_OFF);
                #pragma unroll
                for (int sub = 0; sub < 2; sub++) {
                    const int ks = kp * 2 + sub;
                    u32 a_hi[4], a_lo[4];
                    u32 ad = arow + c * 256 + ks * 32;
                    ldm4(a_hi[0], a_hi[1], a_hi[2], a_hi[3], ad);
                    ldm4(a_lo[0], a_lo[1], a_lo[2], a_lo[3], ad + 2048);
                    const u32 bfh[2] = { bh4[sub * 2], bh4[sub * 2 + 1] };
                    const u32 bfl[2] = { bl4[sub * 2], bl4[sub * 2 + 1] };
                    float* acc = sub ? acc_o : acc_e;
                    mma16816(acc, a_hi, bfh);
                    mma16816(acc, a_hi, bfl);
                    mma16816(acc, a_lo, bfh);
                }
            }
            __syncthreads();
            if (c + 2 < 8) issueV(c + 2, c & 1);
        }

        #pragma unroll
        for (int r = 0; r < 4; r++) acc_e[r] += acc_o[r];

        // epilogue: ctx split -> g_ch/g_cl
        #pragma unroll
        for (int half = 0; half < 2; half++) {
            const int lrow = wm + g + half * 8;
            const int col  = wn8 + t * 2;
            const size_t base = ((size_t)(b8 * N_ + row0 + lrow)) * C_ + h * 64 + col;
            __nv_bfloat16 h0, l0, h1, l1;
            splitf(acc_e[half * 2 + 0], h0, l0);
            splitf(acc_e[half * 2 + 1], h1, l1);
            *(__nv_bfloat162*)(g_ch + base) = __nv_bfloat162(h0, h1);
            *(__nv_bfloat162*)(g_cl + base) = __nv_bfloat162(l0, l1);
        }
    }
}

// ---------------- conversion kernels ----------------
__global__ void __launch_bounds__(256) conv_x(const float* __restrict__ s)
{
    int i = blockIdx.x * 256 + threadIdx.x;
    float4 v = ((const float4*)s)[i];
    __nv_bfloat16 h0, l0, h1, l1, h2, l2, h3, l3;
    splitf(v.x, h0, l0); splitf(v.y, h1, l1);
    splitf(v.z, h2, l2); splitf(v.w, h3, l3);
    __nv_bfloat162* hp = (__nv_bfloat162*)g_xh;
    __nv_bfloat162* lp = (__nv_bfloat162*)g_xl;
    hp[i * 2]     = __nv_bfloat162(h0, h1);
    hp[i * 2 + 1] = __nv_bfloat162(h2, h3);
    lp[i * 2]     = __nv_bfloat162(l0, l1);
    lp[i * 2 + 1] = __nv_bfloat162(l2, l3);
}

template <int W>
__global__ void __launch_bounds__(256) conv_wT(const float* __restrict__ s)
{
    constexpr int R  = C_;
    constexpr int Cc = (W == 0) ? QKVC : C_;
    __nv_bfloat16* dh = (W == 0) ? g_wqh : g_wph;
    __nv_bfloat16* dl = (W == 0) ? g_wql : g_wpl;

    __shared__ float tbuf[32][33];
    const int tx = threadIdx.x & 31, ty = threadIdx.x >> 5;
    const int c0 = blockIdx.x * 32, r0 = blockIdx.y * 32;
    #pragma unroll
    for (int j = 0; j < 4; j++)
        tbuf[ty + j * 8][tx] = s[(size_t)(r0 + ty + j * 8) * Cc + c0 + tx];
    __syncthreads();
    #pragma unroll
    for (int j = 0; j < 4; j++) {
        int i = ty + j * 8;
        float v = tbuf[tx][i];
        __nv_bfloat16 hh, ll;
        splitf(v, hh, ll);
        size_t idx = (size_t)(c0 + i) * R + r0 + tx;
        dh[idx] = hh;
        dl[idx] = ll;
    }
}

// ---------------------------------------------------------------------------
extern "C" void kernel_launch(void* const* d_in, const int* in_sizes, int n_in,
                              void* d_out, int out_size)
{
    const float* x      = (const float*)d_in[0];
    const float* w_qkv  = (const float*)d_in[1];
    const float* w_proj = (const float*)d_in[2];
    const float* b_proj = (const float*)d_in[3];
    float* out  = (float*)d_out;
    float* attn = out + (size_t)M_ * C_;

    const int S128 = 3 * (2 * 128 * 80 + 2 * 128 * 80);   // 122880

    cudaFuncSetAttribute(mma_gemm<0>, cudaFuncAttributeMaxDynamicSharedMemorySize, S128);
    cudaFuncSetAttribute(mma_gemm<3>, cudaFuncAttributeMaxDynamicSharedMemorySize, S128);
    cudaFuncSetAttribute(fused_attn,  cudaFuncAttributeMaxDynamicSharedMemorySize, FA_SMEM);

    // 1) input conversions
    conv_x<<<M_ * C_ / 1024, 256>>>(x);
    conv_wT<0><<<dim3(QKVC / 32, C_ / 32), 256>>>(w_qkv);
    conv_wT<1><<<dim3(C_ / 32, C_ / 32), 256>>>(w_proj);

    // 2) QKV GEMM -> q(scaled)/k/vT splits
    mma_gemm<0><<<dim3(QKVC / 128, M_ / 128), 256, S128>>>(nullptr, nullptr);

    // 3) fused S + softmax + attn write + P@V -> ctx splits
    fused_attn<<<BH_ * 32, 512, FA_SMEM>>>(attn);

    // 4) out = ctx @ w_proj + bias
    mma_gemm<3><<<dim3(C_ / 128, M_ / 128), 256, S128>>>(out, b_proj);
}

// round 7
// speedup vs baseline: 1.1117x; 1.0944x over previous
#include <cuda_runtime.h>
#include <cuda_bf16.h>

typedef unsigned int u32;

#define B_   8
#define N_   1024
#define C_   1024
#define H_   16
#define D_   64
#define M_   (B_ * N_)     // 8192
#define QKVC 3072
#define BH_  (B_ * H_)     // 128

// ---------------- allocation-free scratch (device globals) ----------------
__device__ __align__(256) __nv_bfloat16 g_xh[(size_t)M_ * C_],  g_xl[(size_t)M_ * C_];
__device__ __align__(256) __nv_bfloat16 g_wqh[(size_t)QKVC * C_], g_wql[(size_t)QKVC * C_];
__device__ __align__(256) __nv_bfloat16 g_wph[(size_t)C_ * C_],  g_wpl[(size_t)C_ * C_];
__device__ __align__(256) __nv_bfloat16 g_qh[(size_t)BH_ * N_ * D_], g_ql[(size_t)BH_ * N_ * D_];
__device__ __align__(256) __nv_bfloat16 g_kh[(size_t)BH_ * N_ * D_], g_kl[(size_t)BH_ * N_ * D_];
__device__ __align__(256) __nv_bfloat16 g_vTh[(size_t)BH_ * D_ * N_], g_vTl[(size_t)BH_ * D_ * N_];
__device__ __align__(256) __nv_bfloat16 g_ch[(size_t)M_ * C_],  g_cl[(size_t)M_ * C_];

// ---------------- helpers ----------------
__device__ __forceinline__ u32 smem_u32(const void* p) {
    u32 a;
    asm("{ .reg .u64 t; cvta.to.shared.u64 t, %1; cvt.u32.u64 %0, t; }" : "=r"(a) : "l"(p));
    return a;
}
#define CP16(dst, src) \
    asm volatile("cp.async.cg.shared.global [%0], [%1], 16;" :: "r"(dst), "l"(src) : "memory")
#define CP_COMMIT() asm volatile("cp.async.commit_group;" ::: "memory")
#define CP_WAIT(n)  asm volatile("cp.async.wait_group %0;" :: "n"(n) : "memory")

__device__ __forceinline__ void ldm4(u32& r0, u32& r1, u32& r2, u32& r3, u32 a) {
    asm volatile("ldmatrix.sync.aligned.m8n8.x4.shared.b16 {%0,%1,%2,%3}, [%4];"
        : "=r"(r0), "=r"(r1), "=r"(r2), "=r"(r3) : "r"(a));
}
__device__ __forceinline__ void mma16816(float* c, const u32* a, const u32* b) {
    asm volatile(
        "mma.sync.aligned.m16n8k16.row.col.f32.bf16.bf16.f32 "
        "{%0,%1,%2,%3}, {%4,%5,%6,%7}, {%8,%9}, {%0,%1,%2,%3};"
        : "+f"(c[0]), "+f"(c[1]), "+f"(c[2]), "+f"(c[3])
        : "r"(a[0]), "r"(a[1]), "r"(a[2]), "r"(a[3]), "r"(b[0]), "r"(b[1]));
}
__device__ __forceinline__ void splitf(float v, __nv_bfloat16& h, __nv_bfloat16& l) {
    h = __float2bfloat16(v);
    l = __float2bfloat16(v - __bfloat162float(h));
}
__device__ __forceinline__ u32 pack_hi(float a, float b) {
    __nv_bfloat162 r(__float2bfloat16(a), __float2bfloat16(b));
    return *(u32*)&r;
}

// ---------------------------------------------------------------------------
// Split-bf16 HMMA GEMM (256 threads, 8 warps, MA4 NA4, 3-stage cp.async ring)
// MODE 0: QKV (x * wqkvT)    -> scatter q(scaled)/k/vT hi+lo
// MODE 3: OUT (ctx * wprojT) -> fp32 out + bias
// ---------------------------------------------------------------------------
template <int MODE>
__global__ void __launch_bounds__(256, 1) mma_gemm(float* __restrict__ out_f32,
                                                   const float* __restrict__ bias)
{
    constexpr int NC    = 32;
    constexpr int MA    = 4;
    constexpr int NA    = 4;
    constexpr int APART = 128 * 80;
    constexpr int BPART = 128 * 80;
    constexpr int STAGE = 2 * APART + 2 * BPART;

    extern __shared__ char smem[];
    const u32 sb   = smem_u32(smem);
    const int tid  = threadIdx.x;
    const int wid  = tid >> 5, lane = tid & 31;
    const int g    = lane >> 2, t = lane & 3;
    const int bn   = blockIdx.x * 128;
    const int bm   = blockIdx.y * 128;
    const int wm   = (wid & 1) * 64;
    const int wn   = (wid >> 1) * 32;

    const __nv_bfloat16 *Ah, *Al, *Bh, *Bl;
    if (MODE == 0) {
        Ah = g_xh + (size_t)bm * C_;  Al = g_xl + (size_t)bm * C_;
        Bh = g_wqh + (size_t)bn * C_; Bl = g_wql + (size_t)bn * C_;
    } else {
        Ah = g_ch + (size_t)bm * C_;  Al = g_cl + (size_t)bm * C_;
        Bh = g_wph + (size_t)bn * C_; Bl = g_wpl + (size_t)bn * C_;
    }

    float acc[MA][NA][4];
    #pragma unroll
    for (int i = 0; i < MA; i++)
        #pragma unroll
        for (int j = 0; j < NA; j++)
            #pragma unroll
            for (int r = 0; r < 4; r++) acc[i][j][r] = 0.0f;

    auto issue_loads = [&](int ck, int s) {
        const int kofs = ck * 32;
        const u32 base = sb + s * STAGE;
        #pragma unroll
        for (int i = tid; i < 128 * 4; i += 256) {
            int r = i >> 2, sgm = i & 3;
            u32 off = (u32)(r * 80 + sgm * 16);
            CP16(base + off,         Ah + (size_t)r * C_ + kofs + sgm * 8);
            CP16(base + APART + off, Al + (size_t)r * C_ + kofs + sgm * 8);
        }
        #pragma unroll
        for (int i = tid; i < 128 * 4; i += 256) {
            int r = i >> 2, sgm = i & 3;
            u32 off = (u32)(r * 80 + sgm * 16);
            CP16(base + 2 * APART + off,         Bh + (size_t)r * C_ + kofs + sgm * 8);
            CP16(base + 2 * APART + BPART + off, Bl + (size_t)r * C_ + kofs + sgm * 8);
        }
        CP_COMMIT();
    };

    const u32 arow = (u32)((wm + (lane & 15)) * 80 + ((lane >> 4) << 4));
    const u32 brow = (u32)((wn + (lane & 7) + ((lane >> 4) << 3)) * 80 + (((lane >> 3) & 1) << 4));

    auto do_compute = [&](int s) {
        const u32 abase = sb + s * STAGE;
        const u32 bbase = abase + 2 * APART;
        #pragma unroll
        for (int ks = 0; ks < 2; ks++) {
            const u32 kb = ks * 32;
            u32 a_hi[MA][4], a_lo[MA][4], b_hi[NA][2], b_lo[NA][2];
            #pragma unroll
            for (int ma = 0; ma < MA; ma++) {
                u32 ad = abase + arow + ma * 16 * 80 + kb;
                ldm4(a_hi[ma][0], a_hi[ma][1], a_hi[ma][2], a_hi[ma][3], ad);
                ldm4(a_lo[ma][0], a_lo[ma][1], a_lo[ma][2], a_lo[ma][3], ad + APART);
            }
            #pragma unroll
            for (int p = 0; p < NA / 2; p++) {
                u32 bd = bbase + brow + p * 16 * 80 + kb;
                ldm4(b_hi[2*p][0], b_hi[2*p][1], b_hi[2*p+1][0], b_hi[2*p+1][1], bd);
                ldm4(b_lo[2*p][0], b_lo[2*p][1], b_lo[2*p+1][0], b_lo[2*p+1][1], bd + BPART);
            }
            #pragma unroll
            for (int ma = 0; ma < MA; ma++)
                #pragma unroll
                for (int na = 0; na < NA; na++) {
                    mma16816(acc[ma][na], a_hi[ma], b_hi[na]);
                    mma16816(acc[ma][na], a_hi[ma], b_lo[na]);
                    mma16816(acc[ma][na], a_lo[ma], b_hi[na]);
                }
        }
    };

    issue_loads(0, 0);
    issue_loads(1, 1);
    for (int ck = 0; ck < NC; ck++) {
        const int s = ck % 3;
        if (ck + 2 < NC) { issue_loads(ck + 2, (ck + 2) % 3); CP_WAIT(2); }
        else if (ck + 1 < NC) { CP_WAIT(1); }
        else { CP_WAIT(0); }
        __syncthreads();
        do_compute(s);
        __syncthreads();
    }

    // ---- epilogue ----
    #pragma unroll
    for (int ma = 0; ma < MA; ma++)
        #pragma unroll
        for (int na = 0; na < NA; na++)
            #pragma unroll
            for (int half = 0; half < 2; half++) {
                const int row = bm + wm + ma * 16 + g + half * 8;
                const int col = bn + wn + na * 8 + t * 2;
                float v0 = acc[ma][na][half * 2 + 0];
                float v1 = acc[ma][na][half * 2 + 1];

                if (MODE == 3) {
                    float* dst = out_f32 + (size_t)row * C_ + col;
                    *(float2*)dst = make_float2(v0 + bias[col], v1 + bias[col + 1]);
                } else {  // MODE 0
                    const int which = col >> 10;
                    const int c     = col & 1023;
                    const int h     = c >> 6;
                    const int d0    = c & 63;
                    const int b8    = row >> 10;
                    const int n     = row & 1023;
                    const int bh    = b8 * H_ + h;
                    if (which == 0) {
                        __nv_bfloat16 h0, l0, h1, l1;
                        splitf(v0 * 0.125f, h0, l0); splitf(v1 * 0.125f, h1, l1);
                        const size_t base = ((size_t)bh * N_ + n) * D_ + d0;
                        *(__nv_bfloat162*)(g_qh + base) = __nv_bfloat162(h0, h1);
                        *(__nv_bfloat162*)(g_ql + base) = __nv_bfloat162(l0, l1);
                    } else if (which == 1) {
                        __nv_bfloat16 h0, l0, h1, l1;
                        splitf(v0, h0, l0); splitf(v1, h1, l1);
                        const size_t base = ((size_t)bh * N_ + n) * D_ + d0;
                        *(__nv_bfloat162*)(g_kh + base) = __nv_bfloat162(h0, h1);
                        *(__nv_bfloat162*)(g_kl + base) = __nv_bfloat162(l0, l1);
                    } else {
                        __nv_bfloat16 h0, l0, h1, l1;
                        splitf(v0, h0, l0); splitf(v1, h1, l1);
                        const size_t vb = (size_t)bh * D_ * N_ + n;
                        g_vTh[vb + (size_t)d0 * N_]       = h0;
                        g_vTh[vb + (size_t)(d0 + 1) * N_] = h1;
                        g_vTl[vb + (size_t)d0 * N_]       = l0;
                        g_vTl[vb + (size_t)(d0 + 1) * N_] = l1;
                    }
                }
            }
}

// ---------------------------------------------------------------------------
// Fused S = qk^T -> softmax -> attn fp32 out ONLY (no gmem splits).
// r4 config: 256 threads / 8 warps, warp = 16x32 of the 32x128 chunk.
// ---------------------------------------------------------------------------
#define Q_OFF  0
#define QL_OFF 4608
#define K_OFF  9216
#define KSTG   36864
#define KL_OFF 18432
#define S_OFF  82944
#define S_PIT  4144
#define SS_SMEM (S_OFF + 32 * S_PIT)   // 215552

__global__ void __launch_bounds__(256, 1) sscore_kernel(float* __restrict__ attn)
{
    extern __shared__ char smem[];
    const u32 sb   = smem_u32(smem);
    const int tid  = threadIdx.x;
    const int wid  = tid >> 5, lane = tid & 31;
    const int g    = lane >> 2, t = lane & 3;

    const int bh   = blockIdx.x >> 5;
    const int row0 = (blockIdx.x & 31) * 32;
    const int wm   = (wid & 1) * 16;
    const int wn   = (wid >> 1) * 32;

    const __nv_bfloat16* Qh = g_qh + ((size_t)bh * N_ + row0) * D_;
    const __nv_bfloat16* Ql = g_ql + ((size_t)bh * N_ + row0) * D_;
    const __nv_bfloat16* Kh = g_kh + (size_t)bh * N_ * D_;
    const __nv_bfloat16* Kl = g_kl + (size_t)bh * N_ * D_;

    // Q slab: 32 rows x 128B, pitch 144
    {
        int r = tid >> 3, sgm = tid & 7;
        u32 off = (u32)(r * 144 + sgm * 16);
        *(float4*)(smem + Q_OFF + off)  = *(const float4*)(Qh + r * D_ + sgm * 8);
        *(float4*)(smem + QL_OFF + off) = *(const float4*)(Ql + r * D_ + sgm * 8);
    }

    auto issueK = [&](int c, int s) {
        const u32 base = sb + K_OFF + s * KSTG;
        const size_t ko = (size_t)c * 128 * D_;
        #pragma unroll
        for (int i = tid; i < 128 * 8; i += 256) {
            int r = i >> 3, sgm = i & 7;
            u32 off = (u32)(r * 144 + sgm * 16);
            CP16(base + off,          Kh + ko + r * D_ + sgm * 8);
            CP16(base + KL_OFF + off, Kl + ko + r * D_ + sgm * 8);
        }
        CP_COMMIT();
    };

    const u32 arow = (u32)((wm + (lane & 15)) * 144 + ((lane >> 4) << 4));
    const u32 brow = (u32)((wn + (lane & 7) + ((lane >> 4) << 3)) * 144 + (((lane >> 3) & 1) << 4));

    issueK(0, 0);
    issueK(1, 1);
    for (int c = 0; c < 8; c++) {
        if (c < 7) CP_WAIT(1); else CP_WAIT(0);
        __syncthreads();

        const u32 kb0 = sb + K_OFF + (c & 1) * KSTG;
        float acc[4][4];
        #pragma unroll
        for (int j = 0; j < 4; j++)
            #pragma unroll
            for (int r = 0; r < 4; r++) acc[j][r] = 0.0f;

        #pragma unroll
        for (int ks = 0; ks < 4; ks++) {
            const u32 kb = ks * 32;
            u32 a_hi[4], a_lo[4], b_hi[4][2], b_lo[4][2];
            u32 ad = sb + Q_OFF + arow + kb;
            ldm4(a_hi[0], a_hi[1], a_hi[2], a_hi[3], ad);
            ldm4(a_lo[0], a_lo[1], a_lo[2], a_lo[3], ad + QL_OFF);
            #pragma unroll
            for (int p = 0; p < 2; p++) {
                u32 bd = kb0 + brow + p * 16 * 144 + kb;
                ldm4(b_hi[2*p][0], b_hi[2*p][1], b_hi[2*p+1][0], b_hi[2*p+1][1], bd);
                ldm4(b_lo[2*p][0], b_lo[2*p][1], b_lo[2*p+1][0], b_lo[2*p+1][1], bd + KL_OFF);
            }
            #pragma unroll
            for (int na = 0; na < 4; na++) {
                mma16816(acc[na], a_hi, b_hi[na]);
                mma16816(acc[na], a_hi, b_lo[na]);
                mma16816(acc[na], a_lo, b_hi[na]);
            }
        }

        #pragma unroll
        for (int na = 0; na < 4; na++)
            #pragma unroll
            for (int half = 0; half < 2; half++) {
                int row = wm + g + half * 8;
                int col = c * 128 + wn + na * 8 + t * 2;
                *(float2*)(smem + S_OFF + row * S_PIT + col * 4) =
                    make_float2(acc[na][half * 2], acc[na][half * 2 + 1]);
            }

        __syncthreads();
        if (c + 2 < 8) issueK(c + 2, c & 1);
    }

    // ---- softmax (4 rows per warp) -> attn fp32 only ----
    #pragma unroll
    for (int rr = 0; rr < 4; rr++) {
        const int r = wid * 4 + rr;
        const float* Srow = (const float*)(smem + S_OFF + r * S_PIT);
        float4 f[8];
        float m = -1e30f;
        #pragma unroll
        for (int i = 0; i < 8; i++) {
            f[i] = *(const float4*)(Srow + (lane + i * 32) * 4);
            m = fmaxf(m, fmaxf(fmaxf(f[i].x, f[i].y), fmaxf(f[i].z, f[i].w)));
        }
        #pragma unroll
        for (int o = 16; o > 0; o >>= 1) m = fmaxf(m, __shfl_xor_sync(0xffffffffu, m, o));
        float s = 0.0f;
        #pragma unroll
        for (int i = 0; i < 8; i++) {
            f[i].x = __expf(f[i].x - m); f[i].y = __expf(f[i].y - m);
            f[i].z = __expf(f[i].z - m); f[i].w = __expf(f[i].w - m);
            s += f[i].x + f[i].y + f[i].z + f[i].w;
        }
        #pragma unroll
        for (int o = 16; o > 0; o >>= 1) s += __shfl_xor_sync(0xffffffffu, s, o);
        const float inv = 1.0f / s;

        float* ap = attn + ((size_t)bh * N_ + row0 + r) * N_;
        #pragma unroll
        for (int i = 0; i < 8; i++) {
            *(float4*)(ap + (lane + i * 32) * 4) =
                make_float4(f[i].x * inv, f[i].y * inv, f[i].z * inv, f[i].w * inv);
        }
    }
}

// ---------------------------------------------------------------------------
// AV GEMM: ctx = P @ V, P read as fp32 from attn (d_out), split to bf16 hi/lo
// in smem. 256 threads / 8 warps, tile 128(P rows) x 64(V dims), K chunk 32.
// Smem: A fp32 staging 3 x 18432 | A hi/lo converted 2 x 10240 | V hi/lo ring
// 3 x 10240.  Total = 106496.
// ---------------------------------------------------------------------------
#define AV_ASTG   18432
#define AV_AH_OFF (3 * AV_ASTG)                    // 55296
#define AV_APART  10240
#define AV_B_OFF  (AV_AH_OFF + 2 * AV_APART)       // 75776
#define AV_BSTG   10240
#define AV_SMEM   (AV_B_OFF + 3 * AV_BSTG)         // 106496

__global__ void __launch_bounds__(256, 1) av_gemm(const float* __restrict__ attn)
{
    extern __shared__ char smem[];
    const u32 sb   = smem_u32(smem);
    const int tid  = threadIdx.x;
    const int wid  = tid >> 5, lane = tid & 31;
    const int g    = lane >> 2, t = lane & 3;

    const int bm = blockIdx.y * 128;
    const int z  = blockIdx.z;
    const int b8 = z >> 4, h = z & 15;
    const int wm = (wid & 3) * 32;
    const int wn = (wid >> 2) * 32;

    const float* Ap = attn + (size_t)z * N_ * N_ + (size_t)bm * N_;
    const __nv_bfloat16* Vh = g_vTh + (size_t)z * D_ * N_;
    const __nv_bfloat16* Vl = g_vTl + (size_t)z * D_ * N_;

    float acc[2][4][4];
    #pragma unroll
    for (int i = 0; i < 2; i++)
        #pragma unroll
        for (int j = 0; j < 4; j++)
            #pragma unroll
            for (int r = 0; r < 4; r++) acc[i][j][r] = 0.0f;

    auto issue_loads = [&](int ck, int s) {
        const int kofs = ck * 32;
        // A fp32 staging: 128 rows x 128B, pitch 144
        const u32 abase = sb + s * AV_ASTG;
        #pragma unroll
        for (int i = tid; i < 128 * 8; i += 256) {
            int r = i >> 3, sgm = i & 7;
            CP16(abase + (u32)(r * 144 + sgm * 16), Ap + (size_t)r * N_ + kofs + sgm * 4);
        }
        // V hi/lo: 64 rows x 64B, pitch 80
        const u32 bbase = sb + AV_B_OFF + s * AV_BSTG;
        #pragma unroll
        for (int i = tid; i < 64 * 4; i += 256) {
            int r = i >> 2, sgm = i & 3;
            u32 off = (u32)(r * 80 + sgm * 16);
            CP16(bbase + off,        Vh + (size_t)r * N_ + kofs + sgm * 8);
            CP16(bbase + 5120 + off, Vl + (size_t)r * N_ + kofs + sgm * 8);
        }
        CP_COMMIT();
    };

    const u32 arow = (u32)((wm + (lane & 15)) * 80 + ((lane >> 4) << 4));
    const u32 brow = (u32)((wn + (lane & 7) + ((lane >> 4) << 3)) * 80 + (((lane >> 3) & 1) << 4));

    issue_loads(0, 0);
    issue_loads(1, 1);
    issue_loads(2, 2);
    for (int ck = 0; ck < 32; ck++) {
        const int s = ck % 3;
        if (ck <= 29) CP_WAIT(2);
        else if (ck == 30) CP_WAIT(1);
        else CP_WAIT(0);
        __syncthreads();

        // convert A fp32 stage s -> hi/lo bf16 (80B pitch)
        {
            const char* src = smem + s * AV_ASTG + (tid >> 1) * 144 + (tid & 1) * 64;
            float4 v0 = *(const float4*)(src);
            float4 v1 = *(const float4*)(src + 16);
            float4 v2 = *(const float4*)(src + 32);
            float4 v3 = *(const float4*)(src + 48);
            float fv[16] = { v0.x,v0.y,v0.z,v0.w, v1.x,v1.y,v1.z,v1.w,
                             v2.x,v2.y,v2.z,v2.w, v3.x,v3.y,v3.z,v3.w };
            u32 hw[8], lw[8];
            #pragma unroll
            for (int p = 0; p < 8; p++) {
                __nv_bfloat16 h0, l0, h1, l1;
                splitf(fv[2*p],   h0, l0);
                splitf(fv[2*p+1], h1, l1);
                __nv_bfloat162 hh(h0, h1), ll(l0, l1);
                hw[p] = *(u32*)&hh; lw[p] = *(u32*)&ll;
            }
            char* dh = smem + AV_AH_OFF + (tid >> 1) * 80 + (tid & 1) * 32;
            char* dl = dh + AV_APART;
            *(uint4*)dh        = make_uint4(hw[0], hw[1], hw[2], hw[3]);
            *(uint4*)(dh + 16) = make_uint4(hw[4], hw[5], hw[6], hw[7]);
            *(uint4*)dl        = make_uint4(lw[0], lw[1], lw[2], lw[3]);
            *(uint4*)(dl + 16) = make_uint4(lw[4], lw[5], lw[6], lw[7]);
        }
        __syncthreads();

        // compute
        {
            const u32 ah0 = sb + AV_AH_OFF;
            const u32 bb0 = sb + AV_B_OFF + s * AV_BSTG;
            #pragma unroll
            for (int ks = 0; ks < 2; ks++) {
                const u32 kb = ks * 32;
                u32 a_hi[2][4], a_lo[2][4], b_hi[4][2], b_lo[4][2];
                #pragma unroll
                for (int ma = 0; ma < 2; ma++) {
                    u32 ad = ah0 + arow + ma * 16 * 80 + kb;
                    ldm4(a_hi[ma][0], a_hi[ma][1], a_hi[ma][2], a_hi[ma][3], ad);
                    ldm4(a_lo[ma][0], a_lo[ma][1], a_lo[ma][2], a_lo[ma][3], ad + AV_APART);
                }
                #pragma unroll
                for (int p = 0; p < 2; p++) {
                    u32 bd = bb0 + brow + p * 16 * 80 + kb;
                    ldm4(b_hi[2*p][0], b_hi[2*p][1], b_hi[2*p+1][0], b_hi[2*p+1][1], bd);
                    ldm4(b_lo[2*p][0], b_lo[2*p][1], b_lo[2*p+1][0], b_lo[2*p+1][1], bd + 5120);
                }
                #pragma unroll
                for (int ma = 0; ma < 2; ma++)
                    #pragma unroll
                    for (int na = 0; na < 4; na++) {
                        mma16816(acc[ma][na], a_hi[ma], b_hi[na]);
                        mma16816(acc[ma][na], a_hi[ma], b_lo[na]);
                        mma16816(acc[ma][na], a_lo[ma], b_hi[na]);
                    }
            }
        }
        __syncthreads();
        if (ck + 3 < 32) issue_loads(ck + 3, s);
    }

    // epilogue: ctx split -> g_ch/g_cl
    #pragma unroll
    for (int ma = 0; ma < 2; ma++)
        #pragma unroll
        for (int na = 0; na < 4; na++)
            #pragma unroll
            for (int half = 0; half < 2; half++) {
                const int row = bm + wm + ma * 16 + g + half * 8;
                const int col = wn + na * 8 + t * 2;
                const size_t base = ((size_t)(b8 * N_ + row)) * C_ + h * 64 + col;
                __nv_bfloat16 h0, l0, h1, l1;
                splitf(acc[ma][na][half * 2 + 0], h0, l0);
                splitf(acc[ma][na][half * 2 + 1], h1, l1);
                *(__nv_bfloat162*)(g_ch + base) = __nv_bfloat162(h0, h1);
                *(__nv_bfloat162*)(g_cl + base) = __nv_bfloat162(l0, l1);
            }
}

// ---------------- conversion kernels ----------------
__global__ void __launch_bounds__(256) conv_x(const float* __restrict__ s)
{
    int i = blockIdx.x * 256 + threadIdx.x;
    float4 v = ((const float4*)s)[i];
    __nv_bfloat16 h0, l0, h1, l1, h2, l2, h3, l3;
    splitf(v.x, h0, l0); splitf(v.y, h1, l1);
    splitf(v.z, h2, l2); splitf(v.w, h3, l3);
    __nv_bfloat162* hp = (__nv_bfloat162*)g_xh;
    __nv_bfloat162* lp = (__nv_bfloat162*)g_xl;
    hp[i * 2]     = __nv_bfloat162(h0, h1);
    hp[i * 2 + 1] = __nv_bfloat162(h2, h3);
    lp[i * 2]     = __nv_bfloat162(l0, l1);
    lp[i * 2 + 1] = __nv_bfloat162(l2, l3);
}

template <int W>
__global__ void __launch_bounds__(256) conv_wT(const float* __restrict__ s)
{
    constexpr int R  = C_;
    constexpr int Cc = (W == 0) ? QKVC : C_;
    __nv_bfloat16* dh = (W == 0) ? g_wqh : g_wph;
    __nv_bfloat16* dl = (W == 0) ? g_wql : g_wpl;

    __shared__ float tbuf[32][33];
    const int tx = threadIdx.x & 31, ty = threadIdx.x >> 5;
    const int c0 = blockIdx.x * 32, r0 = blockIdx.y * 32;
    #pragma unroll
    for (int j = 0; j < 4; j++)
        tbuf[ty + j * 8][tx] = s[(size_t)(r0 + ty + j * 8) * Cc + c0 + tx];
    __syncthreads();
    #pragma unroll
    for (int j = 0; j < 4; j++) {
        int i = ty + j * 8;
        float v = tbuf[tx][i];
        __nv_bfloat16 hh, ll;
        splitf(v, hh, ll);
        size_t idx = (size_t)(c0 + i) * R + r0 + tx;
        dh[idx] = hh;
        dl[idx] = ll;
    }
}

// ---------------------------------------------------------------------------
extern "C" void kernel_launch(void* const* d_in, const int* in_sizes, int n_in,
                              void* d_out, int out_size)
{
    const float* x      = (const float*)d_in[0];
    const float* w_qkv  = (const float*)d_in[1];
    const float* w_proj = (const float*)d_in[2];
    const float* b_proj = (const float*)d_in[3];
    float* out  = (float*)d_out;
    float* attn = out + (size_t)M_ * C_;

    const int S128 = 3 * (2 * 128 * 80 + 2 * 128 * 80);   // 122880

    cudaFuncSetAttribute(mma_gemm<0>,  cudaFuncAttributeMaxDynamicSharedMemorySize, S128);
    cudaFuncSetAttribute(mma_gemm<3>,  cudaFuncAttributeMaxDynamicSharedMemorySize, S128);
    cudaFuncSetAttribute(sscore_kernel, cudaFuncAttributeMaxDynamicSharedMemorySize, SS_SMEM);
    cudaFuncSetAttribute(av_gemm,      cudaFuncAttributeMaxDynamicSharedMemorySize, AV_SMEM);

    // 1) input conversions
    conv_x<<<M_ * C_ / 1024, 256>>>(x);
    conv_wT<0><<<dim3(QKVC / 32, C_ / 32), 256>>>(w_qkv);
    conv_wT<1><<<dim3(C_ / 32, C_ / 32), 256>>>(w_proj);

    // 2) QKV GEMM -> q(scaled)/k/vT splits
    mma_gemm<0><<<dim3(QKVC / 128, M_ / 128), 256, S128>>>(nullptr, nullptr);

    // 3) S + softmax -> attn fp32 (no gmem splits)
    sscore_kernel<<<BH_ * 32, 256, SS_SMEM>>>(attn);

    // 4) ctx = attn(fp32) @ V, convert P to hi/lo in-kernel
    av_gemm<<<dim3(1, N_ / 128, BH_), 256, AV_SMEM>>>(attn);

    // 5) out = ctx @ w_proj + bias
    mma_gemm<3><<<dim3(C_ / 128, M_ / 128), 256, S128>>>(out, b_proj);
}